// round 7
// baseline (speedup 1.0000x reference)
#include <cuda_runtime.h>
#include <cuda_fp16.h>
#include <cstdint>
#include <cfloat>

#define BB 2048
#define MM 65536
#define DD 32
#define CTA_B 128
#define CTA_M 128
#define MITER 8
#define CTA_MSPAN (CTA_M * MITER)    // 1024
#define NCHB (MM / CTA_MSPAN)        // 64 (grid.x)
#define NBT  (BB / CTA_B)            // 16 (grid.y)
#define NCHP (NCHB * 2)              // 128 partial chunks (warp_m halves)
#define THREADS 256
#define ROWB 80                      // smem row stride bytes (odd*16 -> LDSM conflict-free)

typedef unsigned int u32;

// ---- global scratch (allocation-free) ----
__device__ __align__(16) __half g_wh[MM * DD];    // fp16 w
__device__ __align__(16) __half g_xh[BB * DD];    // fp16 x
__device__ float g_wn[MM];                        // -||w||^2/2 (exact fp32)
__device__ float g_p3v[BB * NCHP * 3];            // per-(b,chunk) top-3 approx scores
__device__ int   g_p3i[BB * NCHP * 3];

__device__ __forceinline__ u32 smem_u32(const void* p) {
    u32 a;
    asm("{ .reg .u64 t; cvta.to.shared.u64 t, %1; cvt.u32.u64 %0, t; }"
        : "=r"(a) : "l"(p));
    return a;
}

#define LDSM4(r, addr) \
    asm volatile("ldmatrix.sync.aligned.m8n8.x4.shared.b16 {%0,%1,%2,%3}, [%4];" \
        : "=r"((r)[0]), "=r"((r)[1]), "=r"((r)[2]), "=r"((r)[3]) : "r"(addr))

#define MMA16816(c, a, b0v, b1v) \
    asm volatile("mma.sync.aligned.m16n8k16.row.col.f32.f16.f16.f32 " \
        "{%0,%1,%2,%3}, {%4,%5,%6,%7}, {%8,%9}, {%0,%1,%2,%3};" \
        : "+f"((c)[0]), "+f"((c)[1]), "+f"((c)[2]), "+f"((c)[3]) \
        : "r"((a)[0]), "r"((a)[1]), "r"((a)[2]), "r"((a)[3]), "r"(b0v), "r"(b1v))

#define CPA16(d, s)  asm volatile("cp.async.cg.shared.global [%0], [%1], 16;" :: "r"(d), "l"(s))
#define CPA4(d, s)   asm volatile("cp.async.ca.shared.global [%0], [%1], 4;"  :: "r"(d), "l"(s))
#define CPA_COMMIT() asm volatile("cp.async.commit_group;" ::: "memory")
#define CPA_WAIT(n)  asm volatile("cp.async.wait_group %0;" :: "n"(n) : "memory")

// sorted top-3 insert (v0 >= v1 >= v2); strict > keeps earliest index on ties
__device__ __forceinline__ void ins3(float v, int i,
                                     float& v0, float& v1, float& v2,
                                     int& i0, int& i1, int& i2) {
    if (v > v2) {
        if (v > v1) {
            if (v > v0) { v2 = v1; i2 = i1; v1 = v0; i1 = i0; v0 = v; i0 = i; }
            else        { v2 = v1; i2 = i1; v1 = v;  i1 = i; }
        } else          { v2 = v;  i2 = i; }
    }
}

// ---------------- Prepass: fp32 -> fp16 + exact -||w||^2/2 ----------------
__global__ void conv_h(const float* __restrict__ x, const float* __restrict__ w)
{
    const int gt = blockIdx.x * blockDim.x + threadIdx.x;
    const int W_THREADS = MM * 8;
    const bool is_w = gt < W_THREADS;
    const int  t    = is_w ? gt : gt - W_THREADS;
    const int  row  = t >> 3;
    const int  q    = t & 7;
    if (!is_w && row >= BB) return;

    const float4 v = reinterpret_cast<const float4*>(is_w ? w : x)[row * 8 + q];
    __half2 h01 = __halves2half2(__float2half_rn(v.x), __float2half_rn(v.y));
    __half2 h23 = __halves2half2(__float2half_rn(v.z), __float2half_rn(v.w));
    __half2* dst = reinterpret_cast<__half2*>((is_w ? g_wh : g_xh) + row * DD);
    dst[q * 2 + 0] = h01;
    dst[q * 2 + 1] = h23;
    if (is_w) {
        float n = v.x * v.x + v.y * v.y + v.z * v.z + v.w * v.w;
#pragma unroll
        for (int off = 1; off <= 4; off <<= 1)
            n += __shfl_xor_sync(0xffffffffu, n, off);
        if (q == 0) g_wn[row] = -0.5f * n;
    }
}

// ---------------- Main: single-pass fp16 GEMM + fused top-3 ----------------
__global__ __launch_bounds__(THREADS, 2)
void som_mma()
{
    __shared__ __align__(16) char xs[CTA_B * ROWB];
    __shared__ __align__(16) char ws[2][CTA_M * ROWB];
    __shared__ __align__(16) float wn_s[2][CTA_M];

    const int tid  = threadIdx.x;
    const int wid  = tid >> 5;
    const int lane = tid & 31;
    const int b0   = blockIdx.y * CTA_B;
    const int mc0  = blockIdx.x * CTA_MSPAN;

    const u32 xs_b    = smem_u32(xs);
    const u32 ws_b[2] = { smem_u32(ws[0]), smem_u32(ws[1]) };
    const u32 wn_b[2] = { smem_u32(wn_s[0]), smem_u32(wn_s[1]) };

    // x tile (128 rows x 4 float4) + w tile 0
#pragma unroll
    for (int j = 0; j < 2; j++) {
        const int i = tid + j * 256;
        const int r = i >> 2, q = i & 3;
        CPA16(xs_b + r * ROWB + q * 16, &g_xh[(size_t)(b0 + r) * DD + q * 8]);
        CPA16(ws_b[0] + r * ROWB + q * 16, &g_wh[(size_t)(mc0 + r) * DD + q * 8]);
    }
    if (tid < 128) CPA4(wn_b[0] + tid * 4, &g_wn[mc0 + tid]);
    CPA_COMMIT();

    // warp tiling: 4 b-warps x 2 m-warps; warp tile 32b x 64m
    const int warp_b = wid >> 1;
    const int warp_m = wid & 1;
    const int a_row  = warp_b * 32 + (lane & 15);
    const int a_koff = (lane >> 4) * 8;
    const int b_row  = warp_m * 64 + (lane & 7) + ((lane >> 4) << 3);
    const int b_koff = ((lane >> 3) & 1) * 8;
    const int tg     = lane & 3;
    const int mbase  = warp_m * 64 + 2 * tg;

    // per-slot top-3 (slots: bf*2+rh -> distinct b)
    float tv[4][3];
    int   ti[4][3];
#pragma unroll
    for (int s = 0; s < 4; s++)
#pragma unroll
        for (int k = 0; k < 3; k++) { tv[s][k] = -FLT_MAX; ti[s][k] = 0x7fffffff; }

    for (int it = 0; it < MITER; it++) {
        const int cur = it & 1;
        if (it + 1 < MITER) {
            const int nxt = (it + 1) & 1;
            const int m0  = mc0 + (it + 1) * CTA_M;
#pragma unroll
            for (int j = 0; j < 2; j++) {
                const int i = tid + j * 256;
                const int r = i >> 2, q = i & 3;
                CPA16(ws_b[nxt] + r * ROWB + q * 16, &g_wh[(size_t)(m0 + r) * DD + q * 8]);
            }
            if (tid < 128) CPA4(wn_b[nxt] + tid * 4, &g_wn[m0 + tid]);
            CPA_COMMIT();
            CPA_WAIT(1);
        } else {
            CPA_WAIT(0);
        }
        __syncthreads();

        float acc[2][8][4];
#pragma unroll
        for (int bf = 0; bf < 2; bf++)
#pragma unroll
            for (int jj = 0; jj < 8; jj++)
#pragma unroll
                for (int e = 0; e < 4; e++) acc[bf][jj][e] = 0.f;

#pragma unroll
        for (int k2 = 0; k2 < 2; k2++) {
            const int k0 = k2 * 16;
            u32 af[2][4];
#pragma unroll
            for (int bf = 0; bf < 2; bf++)
                LDSM4(af[bf], xs_b + (u32)(a_row + bf * 16) * ROWB + (u32)(k0 + a_koff) * 2);
#pragma unroll
            for (int nbp = 0; nbp < 4; nbp++) {
                u32 bfr[4];
                LDSM4(bfr, ws_b[cur] + (u32)(b_row + nbp * 16) * ROWB + (u32)(k0 + b_koff) * 2);
#pragma unroll
                for (int bf = 0; bf < 2; bf++) {
                    MMA16816(acc[bf][2 * nbp],     af[bf], bfr[0], bfr[1]);
                    MMA16816(acc[bf][2 * nbp + 1], af[bf], bfr[2], bfr[3]);
                }
            }
        }

        const float* wnp = wn_s[cur];
        const int m0g = mc0 + it * CTA_M;
#pragma unroll
        for (int bf = 0; bf < 2; bf++) {
#pragma unroll
            for (int rh = 0; rh < 2; rh++) {
                const int s = bf * 2 + rh;
#pragma unroll
                for (int jj = 0; jj < 8; jj++) {
                    float s0 = acc[bf][jj][rh * 2 + 0] + wnp[mbase + 8 * jj];
                    float s1 = acc[bf][jj][rh * 2 + 1] + wnp[mbase + 8 * jj + 1];
                    int   mg = m0g + mbase + 8 * jj;
                    ins3(s0, mg,     tv[s][0], tv[s][1], tv[s][2], ti[s][0], ti[s][1], ti[s][2]);
                    ins3(s1, mg + 1, tv[s][0], tv[s][1], tv[s][2], ti[s][0], ti[s][1], ti[s][2]);
                }
            }
        }
        __syncthreads();
    }

    // quad merge (same b, 4 m-column groups): top-3 of union = merged top-3s
    const int chunk = blockIdx.x * 2 + warp_m;
#pragma unroll
    for (int s = 0; s < 4; s++) {
#pragma unroll
        for (int off = 1; off <= 2; off <<= 1) {
            float ov[3]; int oi[3];
#pragma unroll
            for (int k = 0; k < 3; k++) {
                ov[k] = __shfl_xor_sync(0xffffffffu, tv[s][k], off);
                oi[k] = __shfl_xor_sync(0xffffffffu, ti[s][k], off);
            }
#pragma unroll
            for (int k = 0; k < 3; k++)
                ins3(ov[k], oi[k], tv[s][0], tv[s][1], tv[s][2], ti[s][0], ti[s][1], ti[s][2]);
        }
        if (tg == 0) {
            const int bf = s >> 1, rh = s & 1;
            const int bg = b0 + warp_b * 32 + bf * 16 + rh * 8 + (lane >> 2);
            const size_t base = ((size_t)bg * NCHP + chunk) * 3;
#pragma unroll
            for (int k = 0; k < 3; k++) { g_p3v[base + k] = tv[s][k]; g_p3i[base + k] = ti[s][k]; }
        }
    }
}

// ---------------- Final: merge 128 chunk top-3s, exact fp32 rescore ----------------
__global__ void som_pick(const float* __restrict__ x, const float* __restrict__ w,
                         const float* __restrict__ grid_flat, float* __restrict__ out)
{
    const int gtid = blockIdx.x * blockDim.x + threadIdx.x;
    const int b    = gtid >> 5;
    const int lane = gtid & 31;
    if (b >= BB) return;

    float v0 = -FLT_MAX, v1 = -FLT_MAX, v2 = -FLT_MAX;
    int   i0 = 0x7fffffff, i1 = 0x7fffffff, i2 = 0x7fffffff;
#pragma unroll
    for (int c = lane; c < NCHP; c += 32) {
        const size_t base = ((size_t)b * NCHP + c) * 3;
#pragma unroll
        for (int k = 0; k < 3; k++)
            ins3(g_p3v[base + k], g_p3i[base + k], v0, v1, v2, i0, i1, i2);
    }
#pragma unroll
    for (int off = 16; off > 0; off >>= 1) {
        float ov[3]; int oi[3];
        ov[0] = __shfl_xor_sync(0xffffffffu, v0, off); oi[0] = __shfl_xor_sync(0xffffffffu, i0, off);
        ov[1] = __shfl_xor_sync(0xffffffffu, v1, off); oi[1] = __shfl_xor_sync(0xffffffffu, i1, off);
        ov[2] = __shfl_xor_sync(0xffffffffu, v2, off); oi[2] = __shfl_xor_sync(0xffffffffu, i2, off);
#pragma unroll
        for (int k = 0; k < 3; k++) ins3(ov[k], oi[k], v0, v1, v2, i0, i1, i2);
    }

    // lanes 0..2: exact fp32 rescore of candidate 'lane'
    float sc = -FLT_MAX;
    int   ci = 0x7fffffff;
    if (lane < 3) {
        ci = (lane == 0) ? i0 : (lane == 1) ? i1 : i2;
        if (ci < MM) {
            const float4* xr = reinterpret_cast<const float4*>(x + (size_t)b * DD);
            const float4* wr = reinterpret_cast<const float4*>(w + (size_t)ci * DD);
            float s = g_wn[ci];
#pragma unroll
            for (int q = 0; q < 8; q++) {
                float4 xv = xr[q], wv = wr[q];
                s += xv.x * wv.x + xv.y * wv.y + xv.z * wv.z + xv.w * wv.w;
            }
            sc = s;
        }
    }
#pragma unroll
    for (int k = 1; k <= 2; k++) {
        float s2 = __shfl_down_sync(0xffffffffu, sc, k);
        int   j2 = __shfl_down_sync(0xffffffffu, ci, k);
        if (lane == 0 && (s2 > sc || (s2 == sc && j2 < ci))) { sc = s2; ci = j2; }
    }
    if (lane == 0) {
        out[b * 2 + 0] = grid_flat[(size_t)ci * 2 + 0];
        out[b * 2 + 1] = grid_flat[(size_t)ci * 2 + 1];
    }
}

extern "C" void kernel_launch(void* const* d_in, const int* in_sizes, int n_in,
                              void* d_out, int out_size)
{
    const float* x = nullptr;
    const float* grid = nullptr;
    const float* w = nullptr;
    for (int i = 0; i < n_in; i++) {
        if      (in_sizes[i] == BB * DD) x    = (const float*)d_in[i];
        else if (in_sizes[i] == MM * 2)  grid = (const float*)d_in[i];
        else if (in_sizes[i] == MM * DD) w    = (const float*)d_in[i];
    }

    const int conv_threads = (MM + BB) * 8;
    conv_h<<<(conv_threads + 255) / 256, 256>>>(x, w);
    dim3 g(NCHB, NBT);
    som_mma<<<g, THREADS>>>();
    som_pick<<<(BB * 32 + 255) / 256, 256>>>(x, w, grid, (float*)d_out);
}

// round 8
// speedup vs baseline: 1.7554x; 1.7554x over previous
#include <cuda_runtime.h>
#include <cuda_fp16.h>
#include <cstdint>
#include <cfloat>

#define BB 2048
#define MM 65536
#define DD 32
#define CTA_B 128
#define CTA_M 128
#define MITER 8
#define CTA_MSPAN (CTA_M * MITER)    // 1024
#define NCHB (MM / CTA_MSPAN)        // 64 (grid.x)
#define NBT  (BB / CTA_B)            // 16 (grid.y)
#define NCHP (NCHB * 2)              // 128 partial chunks (warp_m halves)
#define THREADS 256
#define ROWB 80                      // smem row stride bytes (odd*16 -> LDSM conflict-free)
#define DELTA 0.25f                  // exact-rescore band below approx max

typedef unsigned int u32;

// ---- global scratch (allocation-free) ----
__device__ __align__(16) __half g_wh[MM * DD];    // fp16 w
__device__ __align__(16) __half g_xh[BB * DD];    // fp16 x
__device__ float g_wn[MM];                        // -||w||^2/2 (exact fp32)
__device__ float g_c2v[BB * NCHP * 2];            // per-(b,chunk) top-2 approx scores
__device__ int   g_c2i[BB * NCHP * 2];

__device__ __forceinline__ u32 smem_u32(const void* p) {
    u32 a;
    asm("{ .reg .u64 t; cvta.to.shared.u64 t, %1; cvt.u32.u64 %0, t; }"
        : "=r"(a) : "l"(p));
    return a;
}

#define LDSM4(r, addr) \
    asm volatile("ldmatrix.sync.aligned.m8n8.x4.shared.b16 {%0,%1,%2,%3}, [%4];" \
        : "=r"((r)[0]), "=r"((r)[1]), "=r"((r)[2]), "=r"((r)[3]) : "r"(addr))

#define MMA16816(c, a, b0v, b1v) \
    asm volatile("mma.sync.aligned.m16n8k16.row.col.f32.f16.f16.f32 " \
        "{%0,%1,%2,%3}, {%4,%5,%6,%7}, {%8,%9}, {%0,%1,%2,%3};" \
        : "+f"((c)[0]), "+f"((c)[1]), "+f"((c)[2]), "+f"((c)[3]) \
        : "r"((a)[0]), "r"((a)[1]), "r"((a)[2]), "r"((a)[3]), "r"(b0v), "r"(b1v))

#define CPA16(d, s)  asm volatile("cp.async.cg.shared.global [%0], [%1], 16;" :: "r"(d), "l"(s))
#define CPA4(d, s)   asm volatile("cp.async.ca.shared.global [%0], [%1], 4;"  :: "r"(d), "l"(s))
#define CPA_COMMIT() asm volatile("cp.async.commit_group;" ::: "memory")
#define CPA_WAIT(n)  asm volatile("cp.async.wait_group %0;" :: "n"(n) : "memory")

// Branch-free top-2 insert (strict > : earliest index wins on ties).
__device__ __forceinline__ void top2(float s, int mg,
                                     float& v0, float& v1, int& i0, int& i1) {
    const bool g0 = s > v0;
    const bool g1 = s > v1;
    v1 = g0 ? v0 : (g1 ? s  : v1);
    i1 = g0 ? i0 : (g1 ? mg : i1);
    v0 = g0 ? s  : v0;
    i0 = g0 ? mg : i0;
}
// Merge-with-tiebreak (used once per kernel; branches fine)
__device__ __forceinline__ void merge1(float s, int mg,
                                       float& v0, float& v1, int& i0, int& i1) {
    if (s > v0 || (s == v0 && mg < i0)) {
        v1 = v0; i1 = i0; v0 = s; i0 = mg;
    } else if (s > v1 || (s == v1 && mg < i1)) {
        v1 = s; i1 = mg;
    }
}

// ---------------- Prepass: fp32 -> fp16 + exact -||w||^2/2 ----------------
__global__ void conv_h(const float* __restrict__ x, const float* __restrict__ w)
{
    const int gt = blockIdx.x * blockDim.x + threadIdx.x;
    const int W_THREADS = MM * 8;
    const bool is_w = gt < W_THREADS;
    const int  t    = is_w ? gt : gt - W_THREADS;
    const int  row  = t >> 3;
    const int  q    = t & 7;
    if (!is_w && row >= BB) return;

    const float4 v = reinterpret_cast<const float4*>(is_w ? w : x)[row * 8 + q];
    __half2 h01 = __halves2half2(__float2half_rn(v.x), __float2half_rn(v.y));
    __half2 h23 = __halves2half2(__float2half_rn(v.z), __float2half_rn(v.w));
    __half2* dst = reinterpret_cast<__half2*>((is_w ? g_wh : g_xh) + row * DD);
    dst[q * 2 + 0] = h01;
    dst[q * 2 + 1] = h23;
    if (is_w) {
        float n = v.x * v.x + v.y * v.y + v.z * v.z + v.w * v.w;
#pragma unroll
        for (int off = 1; off <= 4; off <<= 1)
            n += __shfl_xor_sync(0xffffffffu, n, off);
        if (q == 0) g_wn[row] = -0.5f * n;
    }
}

// ---------------- Main: single-pass fp16 GEMM + fused predicated top-2 ----------------
__global__ __launch_bounds__(THREADS, 2)
void som_mma()
{
    __shared__ __align__(16) char xs[CTA_B * ROWB];
    __shared__ __align__(16) char ws[2][CTA_M * ROWB];
    __shared__ __align__(16) float wn_s[2][CTA_M];

    const int tid  = threadIdx.x;
    const int wid  = tid >> 5;
    const int lane = tid & 31;
    const int b0   = blockIdx.y * CTA_B;
    const int mc0  = blockIdx.x * CTA_MSPAN;

    const u32 xs_b    = smem_u32(xs);
    const u32 ws_b[2] = { smem_u32(ws[0]), smem_u32(ws[1]) };
    const u32 wn_b[2] = { smem_u32(wn_s[0]), smem_u32(wn_s[1]) };

#pragma unroll
    for (int j = 0; j < 2; j++) {
        const int i = tid + j * 256;
        const int r = i >> 2, q = i & 3;
        CPA16(xs_b + r * ROWB + q * 16, &g_xh[(size_t)(b0 + r) * DD + q * 8]);
        CPA16(ws_b[0] + r * ROWB + q * 16, &g_wh[(size_t)(mc0 + r) * DD + q * 8]);
    }
    if (tid < 128) CPA4(wn_b[0] + tid * 4, &g_wn[mc0 + tid]);
    CPA_COMMIT();

    const int warp_b = wid >> 1;
    const int warp_m = wid & 1;
    const int a_row  = warp_b * 32 + (lane & 15);
    const int a_koff = (lane >> 4) * 8;
    const int b_row  = warp_m * 64 + (lane & 7) + ((lane >> 4) << 3);
    const int b_koff = ((lane >> 3) & 1) * 8;
    const int tg     = lane & 3;
    const int mbase  = warp_m * 64 + 2 * tg;

    // per-slot top-2 (slots: bf*2+rh -> distinct b)
    float v0[4], v1[4];
    int   i0[4], i1[4];
#pragma unroll
    for (int s = 0; s < 4; s++) {
        v0[s] = -FLT_MAX; v1[s] = -FLT_MAX;
        i0[s] = 0x7fffffff; i1[s] = 0x7fffffff;
    }

    for (int it = 0; it < MITER; it++) {
        const int cur = it & 1;
        if (it + 1 < MITER) {
            const int nxt = (it + 1) & 1;
            const int m0  = mc0 + (it + 1) * CTA_M;
#pragma unroll
            for (int j = 0; j < 2; j++) {
                const int i = tid + j * 256;
                const int r = i >> 2, q = i & 3;
                CPA16(ws_b[nxt] + r * ROWB + q * 16, &g_wh[(size_t)(m0 + r) * DD + q * 8]);
            }
            if (tid < 128) CPA4(wn_b[nxt] + tid * 4, &g_wn[m0 + tid]);
            CPA_COMMIT();
            CPA_WAIT(1);
        } else {
            CPA_WAIT(0);
        }
        __syncthreads();

        float acc[2][8][4];
#pragma unroll
        for (int bf = 0; bf < 2; bf++)
#pragma unroll
            for (int jj = 0; jj < 8; jj++)
#pragma unroll
                for (int e = 0; e < 4; e++) acc[bf][jj][e] = 0.f;

#pragma unroll
        for (int k2 = 0; k2 < 2; k2++) {
            const int k0 = k2 * 16;
            u32 af[2][4];
#pragma unroll
            for (int bf = 0; bf < 2; bf++)
                LDSM4(af[bf], xs_b + (u32)(a_row + bf * 16) * ROWB + (u32)(k0 + a_koff) * 2);
#pragma unroll
            for (int nbp = 0; nbp < 4; nbp++) {
                u32 bfr[4];
                LDSM4(bfr, ws_b[cur] + (u32)(b_row + nbp * 16) * ROWB + (u32)(k0 + b_koff) * 2);
#pragma unroll
                for (int bf = 0; bf < 2; bf++) {
                    MMA16816(acc[bf][2 * nbp],     af[bf], bfr[0], bfr[1]);
                    MMA16816(acc[bf][2 * nbp + 1], af[bf], bfr[2], bfr[3]);
                }
            }
        }

        const float* wnp = wn_s[cur];
        const int m0g = mc0 + it * CTA_M;
#pragma unroll
        for (int bf = 0; bf < 2; bf++) {
#pragma unroll
            for (int rh = 0; rh < 2; rh++) {
                const int s = bf * 2 + rh;
#pragma unroll
                for (int jj = 0; jj < 8; jj++) {
                    float s0 = acc[bf][jj][rh * 2 + 0] + wnp[mbase + 8 * jj];
                    float s1 = acc[bf][jj][rh * 2 + 1] + wnp[mbase + 8 * jj + 1];
                    int   mg = m0g + mbase + 8 * jj;
                    top2(s0, mg,     v0[s], v1[s], i0[s], i1[s]);
                    top2(s1, mg + 1, v0[s], v1[s], i0[s], i1[s]);
                }
            }
        }
        __syncthreads();
    }

    // quad merge: top-2 of union across the 4 m-column lane groups
    const int chunk = blockIdx.x * 2 + warp_m;
#pragma unroll
    for (int s = 0; s < 4; s++) {
#pragma unroll
        for (int off = 1; off <= 2; off <<= 1) {
            float ov0 = __shfl_xor_sync(0xffffffffu, v0[s], off);
            int   oi0 = __shfl_xor_sync(0xffffffffu, i0[s], off);
            float ov1 = __shfl_xor_sync(0xffffffffu, v1[s], off);
            int   oi1 = __shfl_xor_sync(0xffffffffu, i1[s], off);
            merge1(ov0, oi0, v0[s], v1[s], i0[s], i1[s]);
            merge1(ov1, oi1, v0[s], v1[s], i0[s], i1[s]);
        }
        if (tg == 0) {
            const int bf = s >> 1, rh = s & 1;
            const int bg = b0 + warp_b * 32 + bf * 16 + rh * 8 + (lane >> 2);
            const size_t base = ((size_t)bg * NCHP + chunk) * 2;
            g_c2v[base + 0] = v0[s];  g_c2i[base + 0] = i0[s];
            g_c2v[base + 1] = v1[s];  g_c2i[base + 1] = i1[s];
        }
    }
}

// ---------------- Final: approx max over 256 candidates, exact fp32 rescore in band ----------------
__global__ void som_pick(const float* __restrict__ x, const float* __restrict__ w,
                         const float* __restrict__ grid_flat, float* __restrict__ out)
{
    const int gtid = blockIdx.x * blockDim.x + threadIdx.x;
    const int b    = gtid >> 5;
    const int lane = gtid & 31;
    if (b >= BB) return;

    // lane owns chunks {lane, lane+32, lane+64, lane+96} -> 8 candidates
    float cv[8]; int ci[8];
    float amax = -FLT_MAX;
#pragma unroll
    for (int cc = 0; cc < 4; cc++) {
        const int c = lane + cc * 32;
        const size_t base = ((size_t)b * NCHP + c) * 2;
#pragma unroll
        for (int k = 0; k < 2; k++) {
            cv[cc * 2 + k] = g_c2v[base + k];
            ci[cc * 2 + k] = g_c2i[base + k];
            amax = fmaxf(amax, cv[cc * 2 + k]);
        }
    }
#pragma unroll
    for (int off = 16; off > 0; off >>= 1)
        amax = fmaxf(amax, __shfl_xor_sync(0xffffffffu, amax, off));

    // exact rescore of candidates within DELTA of the approx max
    const float thresh = amax - DELTA;
    float es = -FLT_MAX;
    int   ei = 0x7fffffff;
    const float4* xr = reinterpret_cast<const float4*>(x + (size_t)b * DD);
    float4 xv[8];
#pragma unroll
    for (int q = 0; q < 8; q++) xv[q] = xr[q];
#pragma unroll
    for (int k = 0; k < 8; k++) {
        if (cv[k] >= thresh && ci[k] < MM) {
            const float4* wr = reinterpret_cast<const float4*>(w + (size_t)ci[k] * DD);
            float s = g_wn[ci[k]];
#pragma unroll
            for (int q = 0; q < 8; q++) {
                float4 wv = wr[q];
                s += xv[q].x * wv.x + xv[q].y * wv.y + xv[q].z * wv.z + xv[q].w * wv.w;
            }
            if (s > es || (s == es && ci[k] < ei)) { es = s; ei = ci[k]; }
        }
    }
#pragma unroll
    for (int off = 16; off > 0; off >>= 1) {
        float s2 = __shfl_xor_sync(0xffffffffu, es, off);
        int   j2 = __shfl_xor_sync(0xffffffffu, ei, off);
        if (s2 > es || (s2 == es && j2 < ei)) { es = s2; ei = j2; }
    }
    if (lane == 0) {
        out[b * 2 + 0] = grid_flat[(size_t)ei * 2 + 0];
        out[b * 2 + 1] = grid_flat[(size_t)ei * 2 + 1];
    }
}

extern "C" void kernel_launch(void* const* d_in, const int* in_sizes, int n_in,
                              void* d_out, int out_size)
{
    const float* x = nullptr;
    const float* grid = nullptr;
    const float* w = nullptr;
    for (int i = 0; i < n_in; i++) {
        if      (in_sizes[i] == BB * DD) x    = (const float*)d_in[i];
        else if (in_sizes[i] == MM * 2)  grid = (const float*)d_in[i];
        else if (in_sizes[i] == MM * DD) w    = (const float*)d_in[i];
    }

    const int conv_threads = (MM + BB) * 8;
    conv_h<<<(conv_threads + 255) / 256, 256>>>(x, w);
    dim3 g(NCHB, NBT);
    som_mma<<<g, THREADS>>>();
    som_pick<<<(BB * 32 + 255) / 256, 256>>>(x, w, grid, (float*)d_out);
}